// round 6
// baseline (speedup 1.0000x reference)
#include <cuda_runtime.h>
#include <math.h>

// HorizonReward: collapsed UT cartpole rollout, u-affine restructured.
// The loop-carried critical cycle is u -> policy -> u. Dynamics and the
// policy input are affine in u, so all per-step coefficient work (angles,
// dynamics coefficients, deviation coefficients, policy l-vector
// coefficients) is u-independent and overlaps the previous step's SHFL
// reduction. Post-u path: clamp -> 4 FFMA2 -> q tree -> ex2 -> 5 shfl.
// Covariance math identical to verified R4/R5 (centered B/D, x5-prescaled
// so chol() yields sqrt(5)*S directly).

typedef unsigned long long u64;

__device__ __forceinline__ u64 pk(float lo, float hi) {
    u64 r; asm("mov.b64 %0,{%1,%2};" : "=l"(r) : "f"(lo), "f"(hi)); return r;
}
__device__ __forceinline__ void upk(u64 a, float& x, float& y) {
    asm("mov.b64 {%0,%1},%2;" : "=f"(x), "=f"(y) : "l"(a));
}
__device__ __forceinline__ u64 sp2(float s) { return pk(s, s); }
__device__ __forceinline__ u64 fma2_(u64 a, u64 b, u64 c) {
    u64 d; asm("fma.rn.f32x2 %0,%1,%2,%3;" : "=l"(d) : "l"(a), "l"(b), "l"(c)); return d;
}
__device__ __forceinline__ u64 mul2_(u64 a, u64 b) {
    u64 d; asm("mul.rn.f32x2 %0,%1,%2;" : "=l"(d) : "l"(a), "l"(b)); return d;
}
__device__ __forceinline__ u64 add2_(u64 a, u64 b) {
    u64 d; asm("add.rn.f32x2 %0,%1,%2;" : "=l"(d) : "l"(a), "l"(b)); return d;
}
__device__ __forceinline__ float rcp_(float x) {
    float r; asm("rcp.approx.f32 %0,%1;" : "=f"(r) : "f"(x)); return r;
}
__device__ __forceinline__ float ex2_(float x) {
    float r; asm("ex2.approx.f32 %0,%1;" : "=f"(r) : "f"(x)); return r;
}

__global__ __launch_bounds__(32, 1)
void horizon_reward_kernel(const float* __restrict__ p, float* __restrict__ out)
{
    const int lane = threadIdx.x & 31;

    // ---- policy params, packed (RBF lane in lo, RBF lane+32 in hi; padded) ----
    u64 nmu2[4], L2[10];
    float wa, wb;
    {
        const int j = lane, j2 = lane + 32;
        const bool hb = (j2 < 50);
        wa = p[j]; wb = hb ? p[j2] : 0.f;
        #pragma unroll
        for (int k = 0; k < 4; ++k)
            nmu2[k] = pk(-p[50 + k * 50 + j], hb ? -p[50 + k * 50 + j2] : 0.f);
        #pragma unroll
        for (int t = 0; t < 10; ++t)
            L2[t] = pk(p[250 + j * 10 + t], hb ? p[250 + j2 * 10 + t] : 0.f);
    }

    const float DT = 0.05f;
    const float W0 = 0.2f, WI = 0.1f;
    const float K1 = 0.05f / 1.1f;
    const float K3 = 0.5f * (4.0f / 3.0f);
    const float K2 = 0.5f * 0.1f / 1.1f;
    const float INV11 = 1.0f / 1.1f;
    const float DIAG_ADD5 = 5.0f * (0.01f * 0.05f + 2.0f * 1e-6f);

    const u64 CPM     = pk(1.f, -1.f);
    const u64 DT2     = sp2(DT);
    const u64 K1_2    = sp2(K1);
    const u64 NK1_2   = sp2(-K1);
    const u64 C98_2   = sp2(9.8f);
    const u64 NM1_2   = sp2(-1.f);
    const u64 INV11_2 = sp2(INV11);
    const u64 NINV11_2 = sp2(-INV11);
    const u64 NL2E2   = sp2(-1.4426950408889634f);

    // ---- state ----
    float m0 = 0.f, m1 = 0.f, m2 = 0.1f, m3 = 0.f;
    const float r0i = 2.23606797749979f * 1e-3f;
    float S00 = r0i, S10 = 0.f, S20 = 0.f, S30 = 0.f;
    float S11 = r0i, S21 = 0.f, S31 = 0.f;
    float S22 = r0i, S32 = 0.f;
    float S33 = r0i;

    // ---- initial raw (unclamped) policy at m ----
    float accRaw;
    {
        u64 d0 = add2_(sp2(m0), nmu2[0]);
        u64 d1 = add2_(sp2(m1), nmu2[1]);
        u64 d2 = add2_(sp2(m2), nmu2[2]);
        u64 d3 = add2_(sp2(m3), nmu2[3]);
        u64 l0 = mul2_(L2[0], d0);
        l0 = fma2_(L2[4], d1, l0); l0 = fma2_(L2[5], d2, l0); l0 = fma2_(L2[7], d3, l0);
        u64 l1 = mul2_(L2[1], d1); l1 = fma2_(L2[6], d2, l1); l1 = fma2_(L2[8], d3, l1);
        u64 l2 = mul2_(L2[2], d2); l2 = fma2_(L2[9], d3, l2);
        u64 l3 = mul2_(L2[3], d3);
        u64 q = fma2_(l1, l1, mul2_(l0, l0));
        q = add2_(q, fma2_(l3, l3, mul2_(l2, l2)));
        q = mul2_(q, NL2E2);
        float qa, qb; upk(q, qa, qb);
        accRaw = fmaf(wa, ex2_(qa), wb * ex2_(qb));
        #pragma unroll
        for (int o = 16; o > 0; o >>= 1)
            accRaw += __shfl_xor_sync(0xffffffffu, accRaw, o);
    }

    float reward = 0.f;

    #pragma unroll 1
    for (int t = 0; t < 60; ++t) {
        // ================= u-independent coefficient phase =================
        // angles (exact MUFU sincos — magnitude-safe) + denominators
        const float thp0 = m2 + S20, thm0 = m2 - S20;
        const float thp1 = m2 + S21, thm1 = m2 - S21;
        const float thp2 = m2 + S22, thm2 = m2 - S22;
        const float scc = __sinf(m2),  ccc = __cosf(m2);
        const float sp0 = __sinf(thp0), cp0 = __cosf(thp0);
        const float sm0 = __sinf(thm0), cm0 = __cosf(thm0);
        const float sp1 = __sinf(thp1), cp1 = __cosf(thp1);
        const float sm1 = __sinf(thm1), cm1 = __cosf(thm1);
        const float sp2v = __sinf(thp2), cp2 = __cosf(thp2);
        const float sm2v = __sinf(thm2), cm2 = __cosf(thm2);
        const float rdc = rcp_(fmaf(-K2 * ccc, ccc, K3));
        const float rp0 = rcp_(fmaf(-K2 * cp0, cp0, K3));
        const float rm0 = rcp_(fmaf(-K2 * cm0, cm0, K3));
        const float rp1 = rcp_(fmaf(-K2 * cp1, cp1, K3));
        const float rm1 = rcp_(fmaf(-K2 * cm1, cm1, K3));
        const float rp2 = rcp_(fmaf(-K2 * cp2, cp2, K3));
        const float rm2 = rcp_(fmaf(-K2 * cm2, cm2, K3));

        u64 sn2[4], cs2[4], rd2[4];
        sn2[0] = pk(sp0, sm0);   cs2[0] = pk(cp0, cm0);  rd2[0] = pk(rp0, rm0);
        sn2[1] = pk(sp1, sm1);   cs2[1] = pk(cp1, cm1);  rd2[1] = pk(rp1, rm1);
        sn2[2] = pk(sp2v, sm2v); cs2[2] = pk(cp2, cm2);  rd2[2] = pk(rp2, rm2);
        sn2[3] = sp2(scc);       cs2[3] = sp2(ccc);      rd2[3] = sp2(rdc);

        const u64 pmS10 = mul2_(sp2(S10), CPM);
        const u64 pmS11 = mul2_(sp2(S11), CPM);
        const u64 pmS30 = mul2_(sp2(S30), CPM);
        const u64 pmS31 = mul2_(sp2(S31), CPM);
        const u64 pmS32 = mul2_(sp2(S32), CPM);
        const u64 pmS33 = mul2_(sp2(S33), CPM);
        const u64 m3_2 = sp2(m3);
        u64 thd2[4];
        thd2[0] = add2_(pmS30, m3_2);
        thd2[1] = add2_(pmS31, m3_2);
        thd2[2] = add2_(pmS32, m3_2);
        thd2[3] = add2_(pmS33, m3_2);

        // dynamics coefficients: xacc = xa0 + xaU*u ; thacc = ta0 + taU*u
        u64 xa0[4], xaU[4], ta0[4], taU[4];
        #pragma unroll
        for (int j = 0; j < 4; ++j) {
            u64 tq    = mul2_(thd2[j], thd2[j]);
            u64 tk    = mul2_(tq, K1_2);
            u64 temp0 = mul2_(tk, sn2[j]);
            u64 g     = mul2_(sn2[j], C98_2);
            u64 ct    = mul2_(cs2[j], temp0);
            u64 num   = fma2_(ct, NM1_2, g);            // 9.8 s - c*temp0
            ta0[j]    = mul2_(num, rd2[j]);
            u64 crd   = mul2_(cs2[j], rd2[j]);
            taU[j]    = mul2_(crd, NINV11_2);           // -(c rd)/1.1
            xa0[j]    = fma2_(mul2_(ta0[j], cs2[j]), NK1_2, temp0);
            xaU[j]    = fma2_(mul2_(taU[j], cs2[j]), NK1_2, INV11_2);
        }
        // center scalar coefficients
        float xa0c, xaUc, ta0c, taUc;
        {
            float temp0 = K1 * m3 * m3 * scc;
            ta0c = fmaf(-ccc, temp0, 9.8f * scc) * rdc;
            taUc = -(ccc * rdc) * INV11;
            xa0c = fmaf(-K1, ta0c * ccc, temp0);
            xaUc = fmaf(-K1, taUc * ccc, INV11);
        }

        // weighted coefficient means
        float xbar0, xbarU, tbar0, tbarU;
        {
            u64 s = add2_(add2_(xa0[0], xa0[1]), add2_(xa0[2], xa0[3]));
            float lo, hi; upk(s, lo, hi);
            xbar0 = fmaf(W0, xa0c, WI * (lo + hi));
            s = add2_(add2_(xaU[0], xaU[1]), add2_(xaU[2], xaU[3]));
            upk(s, lo, hi);
            xbarU = fmaf(W0, xaUc, WI * (lo + hi));
            s = add2_(add2_(ta0[0], ta0[1]), add2_(ta0[2], ta0[3]));
            upk(s, lo, hi);
            tbar0 = fmaf(W0, ta0c, WI * (lo + hi));
            s = add2_(add2_(taU[0], taU[1]), add2_(taU[2], taU[3]));
            upk(s, lo, hi);
            tbarU = fmaf(W0, taUc, WI * (lo + hi));
        }

        // next-mean coefficients (n0,n2 exact; n1,n3 affine in u)
        const float n0  = fmaf(DT, m1, m0);
        const float n2  = fmaf(DT, m3, m2);
        const float n10 = fmaf(DT, xbar0, m1);
        const float n1U = DT * xbarU;
        const float n30 = fmaf(DT, tbar0, m3);
        const float n3U = DT * tbarU;

        // centered deviation coefficients
        const u64 nxb0 = sp2(-xbar0), nxbU = sp2(-xbarU);
        const u64 ntb0 = sp2(-tbar0), ntbU = sp2(-tbarU);
        u64 dv10[4], dv1U[4], dv30[4], dv3U[4];
        #pragma unroll
        for (int j = 0; j < 4; ++j) {
            dv10[j] = add2_(xa0[j], nxb0);
            dv1U[j] = add2_(xaU[j], nxbU);
            dv30[j] = add2_(ta0[j], ntb0);
            dv3U[j] = add2_(taU[j], ntbU);
        }
        const float dc10 = xa0c - xbar0, dc1U = xaUc - xbarU;
        const float dc30 = ta0c - tbar0, dc3U = taUc - tbarU;

        // linear-coordinate deviations (u-independent)
        const float A0 = fmaf(DT, S10, S00);
        const float A1 = DT * S11;
        const float C0 = fmaf(DT, S30, S20);
        const float C1 = fmaf(DT, S31, S21);
        const float C2 = fmaf(DT, S32, S22);
        const float C3 = DT * S33;

        // policy l-vector coefficients: l_k = l_k0 + l_kU * u
        const u64 d0c = add2_(sp2(n0), nmu2[0]);
        const u64 d2c = add2_(sp2(n2), nmu2[2]);
        const u64 d10 = add2_(sp2(n10), nmu2[1]);
        const u64 d30 = add2_(sp2(n30), nmu2[3]);
        const u64 U1 = sp2(n1U), U3 = sp2(n3U);
        u64 l00 = mul2_(L2[0], d0c);
        l00 = fma2_(L2[4], d10, l00); l00 = fma2_(L2[5], d2c, l00); l00 = fma2_(L2[7], d30, l00);
        const u64 l0U = fma2_(L2[4], U1, mul2_(L2[7], U3));
        u64 l10 = mul2_(L2[1], d10);
        l10 = fma2_(L2[6], d2c, l10); l10 = fma2_(L2[8], d30, l10);
        const u64 l1U = fma2_(L2[1], U1, mul2_(L2[8], U3));
        u64 l20 = mul2_(L2[2], d2c);
        l20 = fma2_(L2[9], d30, l20);
        const u64 l2U = mul2_(L2[9], U3);
        const u64 l30 = mul2_(L2[3], d30);
        const u64 l3U = mul2_(L2[3], U3);

        // ================= u arrives (clamp previous raw sum) ==============
        const float u = fminf(fmaxf(accRaw, -10.f), 10.f);
        const u64 u2 = sp2(u);

        // next policy raw sum — start the shfl chain ASAP
        {
            u64 l0 = fma2_(l0U, u2, l00);
            u64 l1 = fma2_(l1U, u2, l10);
            u64 l2 = fma2_(l2U, u2, l20);
            u64 l3 = fma2_(l3U, u2, l30);
            u64 q = fma2_(l1, l1, mul2_(l0, l0));
            q = add2_(q, fma2_(l3, l3, mul2_(l2, l2)));
            q = mul2_(q, NL2E2);
            float qa, qb; upk(q, qa, qb);
            accRaw = fmaf(wa, ex2_(qa), wb * ex2_(qb));
            #pragma unroll
            for (int o = 16; o > 0; o >>= 1)
                accRaw += __shfl_xor_sync(0xffffffffu, accRaw, o);
        }

        // state update + covariance (fills the shfl shadow)
        const float n1 = fmaf(n1U, u, n10);
        const float n3 = fmaf(n3U, u, n30);

        u64 B2[4], D2[4];
        {
            u64 v;
            v = fma2_(dv1U[0], u2, dv10[0]); B2[0] = fma2_(v, DT2, pmS10);
            v = fma2_(dv1U[1], u2, dv10[1]); B2[1] = fma2_(v, DT2, pmS11);
            v = fma2_(dv1U[2], u2, dv10[2]); B2[2] = mul2_(v, DT2);
            v = fma2_(dv1U[3], u2, dv10[3]); B2[3] = mul2_(v, DT2);
            v = fma2_(dv3U[0], u2, dv30[0]); D2[0] = fma2_(v, DT2, pmS30);
            v = fma2_(dv3U[1], u2, dv30[1]); D2[1] = fma2_(v, DT2, pmS31);
            v = fma2_(dv3U[2], u2, dv30[2]); D2[2] = fma2_(v, DT2, pmS32);
            v = fma2_(dv3U[3], u2, dv30[3]); D2[3] = fma2_(v, DT2, pmS33);
        }
        const float Bc = DT * fmaf(dc1U, u, dc10);
        const float Dc = DT * fmaf(dc3U, u, dc30);

        // covariance (x5 prescaled)
        float c00 = fmaf(A1, A1, A0 * A0) + DIAG_ADD5;
        const float c20 = fmaf(A1, C1, A0 * C0);
        float c22 = fmaf(C3, C3, fmaf(C2, C2, fmaf(C1, C1, C0 * C0))) + DIAG_ADD5;

        u64 sBB = mul2_(B2[0], B2[0]);
        sBB = fma2_(B2[1], B2[1], sBB);
        sBB = fma2_(B2[2], B2[2], sBB);
        sBB = fma2_(B2[3], B2[3], sBB);
        u64 sDD = mul2_(D2[0], D2[0]);
        sDD = fma2_(D2[1], D2[1], sDD);
        sDD = fma2_(D2[2], D2[2], sDD);
        sDD = fma2_(D2[3], D2[3], sDD);
        u64 sBD = mul2_(B2[0], D2[0]);
        sBD = fma2_(B2[1], D2[1], sBD);
        sBD = fma2_(B2[2], D2[2], sBD);
        sBD = fma2_(B2[3], D2[3], sBD);
        float bbl, bbh, ddl, ddh, bdl, bdh;
        upk(sBB, bbl, bbh); upk(sDD, ddl, ddh); upk(sBD, bdl, bdh);
        float c11 = fmaf(0.5f, bbl + bbh, Bc * Bc) + DIAG_ADD5;
        float c33 = fmaf(0.5f, ddl + ddh, Dc * Dc) + DIAG_ADD5;
        const float c31 = fmaf(0.5f, bdl + bdh, Bc * Dc);

        float bp0, bm0, bp1, bm1, bp2, bm2, bp3, bm3;
        upk(B2[0], bp0, bm0); upk(B2[1], bp1, bm1);
        upk(B2[2], bp2, bm2); upk(B2[3], bp3, bm3);
        float dp0, dm0, dp1, dm1, dp2, dm2, dp3, dm3;
        upk(D2[0], dp0, dm0); upk(D2[1], dp1, dm1);
        upk(D2[2], dp2, dm2); upk(D2[3], dp3, dm3);
        const float gB0 = bp0 - bm0, gB1 = bp1 - bm1, gB2 = bp2 - bm2, gB3 = bp3 - bm3;
        const float gD0 = dp0 - dm0, gD1 = dp1 - dm1, gD2 = dp2 - dm2, gD3 = dp3 - dm3;
        const float c10 = 0.5f * fmaf(A1, gB1, A0 * gB0);
        const float c30 = 0.5f * fmaf(A1, gD1, A0 * gD0);
        const float c21 = 0.5f * fmaf(C3, gB3, fmaf(C2, gB2, fmaf(C1, gB1, C0 * gB0)));
        const float c32 = 0.5f * fmaf(C3, gD3, fmaf(C2, gD2, fmaf(C1, gD1, C0 * gD0)));

        // reward: m^T Q m + 0.2 * trace(Q * 5C)
        const float qq = fmaf(n0, n0, fmaf(n1, n1, fmaf(10.f * n2, n2, n3 * n3)));
        const float tr = c00 + c11 + fmaf(10.f, c22, c33);
        reward -= fmaf(0.2f, tr, qq);

        // 4x4 Cholesky via rsqrt
        const float r0 = rsqrtf(c00);
        S00 = c00 * r0;
        S10 = c10 * r0; S20 = c20 * r0; S30 = c30 * r0;
        const float a11 = fmaf(-S10, S10, c11);
        const float r1 = rsqrtf(a11);
        S11 = a11 * r1;
        S21 = fmaf(-S20, S10, c21) * r1;
        S31 = fmaf(-S30, S10, c31) * r1;
        const float a22 = fmaf(-S21, S21, fmaf(-S20, S20, c22));
        const float r2 = rsqrtf(a22);
        S22 = a22 * r2;
        S32 = fmaf(-S31, S21, fmaf(-S30, S20, c32)) * r2;
        const float a33 = fmaf(-S32, S32, fmaf(-S31, S31, fmaf(-S30, S30, c33)));
        S33 = a33 * rsqrtf(a33);

        m0 = n0; m1 = n1; m2 = n2; m3 = n3;
    }

    if (lane == 0) out[0] = reward;
}

extern "C" void kernel_launch(void* const* d_in, const int* in_sizes, int n_in,
                              void* d_out, int out_size) {
    (void)in_sizes; (void)n_in; (void)out_size;
    horizon_reward_kernel<<<1, 32>>>((const float*)d_in[0], (float*)d_out);
}

// round 7
// speedup vs baseline: 1.2980x; 1.2980x over previous
#include <cuda_runtime.h>
#include <math.h>

// HorizonReward: collapsed UT cartpole rollout — SIMT sigma points.
// Lanes 0-8 (dup 16-24) each own one sigma point: dynamics is ONE scalar
// chain instead of 9 redundant copies (fp32 FMA pipe is the bottleneck;
// f32x2 is flop-rate-neutral, so the only win is fewer FMA-equivalents).
// Covariance via 9 parallel butterfly reductions of UNCENTERED moments:
//   cross entries pair with exactly-zero-mean linear devs (no centering),
//   diagonals use c = Sum(cw*y^2) - 5*delta^2 (benign cancellation).
// Linear-coordinate entries (c00,c20,c22) analytic from S (exact).
// Everything x5-prescaled so chol() yields sqrt(5)*S directly.
// Policy: R5's verified packed 2-RBF-per-lane form (input n is uniform).

typedef unsigned long long u64;

__device__ __forceinline__ u64 pk(float lo, float hi) {
    u64 r; asm("mov.b64 %0,{%1,%2};" : "=l"(r) : "f"(lo), "f"(hi)); return r;
}
__device__ __forceinline__ void upk(u64 a, float& x, float& y) {
    asm("mov.b64 {%0,%1},%2;" : "=f"(x), "=f"(y) : "l"(a));
}
__device__ __forceinline__ u64 sp2(float s) { return pk(s, s); }
__device__ __forceinline__ u64 fma2_(u64 a, u64 b, u64 c) {
    u64 d; asm("fma.rn.f32x2 %0,%1,%2,%3;" : "=l"(d) : "l"(a), "l"(b), "l"(c)); return d;
}
__device__ __forceinline__ u64 mul2_(u64 a, u64 b) {
    u64 d; asm("mul.rn.f32x2 %0,%1,%2;" : "=l"(d) : "l"(a), "l"(b)); return d;
}
__device__ __forceinline__ u64 add2_(u64 a, u64 b) {
    u64 d; asm("add.rn.f32x2 %0,%1,%2;" : "=l"(d) : "l"(a), "l"(b)); return d;
}
__device__ __forceinline__ float rcp_(float x) {
    float r; asm("rcp.approx.f32 %0,%1;" : "=f"(r) : "f"(x)); return r;
}
__device__ __forceinline__ float ex2_(float x) {
    float r; asm("ex2.approx.f32 %0,%1;" : "=f"(r) : "f"(x)); return r;
}

// packed policy: RBF-A in lo lane, RBF-B in hi lane of every f32x2.
__device__ __forceinline__ float policy_u2(
    float n0, float n1, float n2, float n3,
    float wa, float wb, const u64* nmu2, const u64* L2, u64 NL2E2)
{
    u64 d0 = add2_(sp2(n0), nmu2[0]);
    u64 d1 = add2_(sp2(n1), nmu2[1]);
    u64 d2 = add2_(sp2(n2), nmu2[2]);
    u64 d3 = add2_(sp2(n3), nmu2[3]);
    u64 l0 = mul2_(L2[0], d0);
    l0 = fma2_(L2[4], d1, l0); l0 = fma2_(L2[5], d2, l0); l0 = fma2_(L2[7], d3, l0);
    u64 l1 = mul2_(L2[1], d1); l1 = fma2_(L2[6], d2, l1); l1 = fma2_(L2[8], d3, l1);
    u64 l2 = mul2_(L2[2], d2); l2 = fma2_(L2[9], d3, l2);
    u64 l3 = mul2_(L2[3], d3);
    u64 q = fma2_(l1, l1, mul2_(l0, l0));
    q = add2_(q, fma2_(l3, l3, mul2_(l2, l2)));
    q = mul2_(q, NL2E2);
    float qa, qb; upk(q, qa, qb);
    float acc = fmaf(wa, ex2_(qa), wb * ex2_(qb));
    #pragma unroll
    for (int o = 16; o > 0; o >>= 1)
        acc += __shfl_xor_sync(0xffffffffu, acc, o);
    return fminf(fmaxf(acc, -10.f), 10.f);
}

__global__ __launch_bounds__(32, 1)
void horizon_reward_kernel(const float* __restrict__ p, float* __restrict__ out)
{
    const int lane = threadIdx.x & 31;

    // ---- policy params, packed (RBF lane in lo, RBF lane+32 in hi; padded) ----
    u64 nmu2[4], L2[10];
    float wa, wb;
    {
        const int j = lane, j2 = lane + 32;
        const bool hb = (j2 < 50);
        wa = p[j]; wb = hb ? p[j2] : 0.f;
        #pragma unroll
        for (int k = 0; k < 4; ++k)
            nmu2[k] = pk(-p[50 + k * 50 + j], hb ? -p[50 + k * 50 + j2] : 0.f);
        #pragma unroll
        for (int t = 0; t < 10; ++t)
            L2[t] = pk(p[250 + j * 10 + t], hb ? p[250 + j2 * 10 + t] : 0.f);
    }

    const float DT = 0.05f;
    const float K1 = 0.05f / 1.1f;
    const float K3 = 0.5f * (4.0f / 3.0f);
    const float K2 = 0.5f * 0.1f / 1.1f;
    const float INV11 = 1.0f / 1.1f;
    const float DIAG_ADD5 = 5.0f * (0.01f * 0.05f + 2.0f * 1e-6f);
    const u64 NL2E2 = sp2(-1.4426950408889634f);

    // ---- per-lane sigma-point role: p = lane&15 (0=center, 1-4 = +col,
    //      5-8 = -col, 9-15 dummy); lanes 16-31 duplicate (weights halved) ----
    const int pt = lane & 15;
    const int col = (pt == 0) ? 3 : ((pt - 1) & 3);   // center -> col3 w/ sgn 0
    const float sgn = (pt >= 1 && pt <= 4) ? 1.f : ((pt >= 5 && pt <= 8) ? -1.f : 0.f);
    const bool valid = (pt <= 8);
    const float wgt = (pt == 0) ? 0.1f  : (valid ? 0.05f : 0.f);  // w/2
    const float cw  = (pt == 0) ? 0.5f  : (valid ? 0.25f : 0.f);  // 5*w/2
    const bool isC0 = (col == 0), isC1 = (col == 1), isC2 = (col == 2);

    // ---- state: mean + scaled Cholesky sqrt(5)*chol(C) (uniform in warp) ----
    float m0 = 0.f, m1 = 0.f, m2 = 0.1f, m3 = 0.f;
    const float r0i = 2.23606797749979f * 1e-3f;
    float S00 = r0i, S10 = 0.f, S20 = 0.f, S30 = 0.f;
    float S11 = r0i, S21 = 0.f, S31 = 0.f;
    float S22 = r0i, S32 = 0.f;
    float S33 = r0i;

    float u = policy_u2(m0, m1, m2, m3, wa, wb, nmu2, L2, NL2E2);
    float reward = 0.f;

    #pragma unroll 1
    for (int t = 0; t < 60; ++t) {
        const float ud = u * INV11;

        // ---- per-lane sigma offsets r_k = sgn * S[k][col] (SELs on ALU pipe) ----
        const float r0s = isC0 ? S00 : 0.f;
        const float r1s = isC0 ? S10 : (isC1 ? S11 : 0.f);
        const float r2s = isC0 ? S20 : (isC1 ? S21 : (isC2 ? S22 : 0.f));
        const float r3s = isC0 ? S30 : (isC1 ? S31 : (isC2 ? S32 : S33));
        const float r0 = sgn * r0s, r1 = sgn * r1s, r2 = sgn * r2s, r3 = sgn * r3s;

        // ---- ONE scalar dynamics chain per lane ----
        const float th = m2 + r2, thd = m3 + r3;
        const float s = __sinf(th), c = __cosf(th);
        const float rd = rcp_(fmaf(-K2 * c, c, K3));
        const float tk = (thd * thd) * K1;
        const float temp = fmaf(tk, s, ud);
        const float num = fmaf(-c, temp, 9.8f * s);
        const float ta = num * rd;
        const float xa = fmaf(-K1, ta * c, temp);

        // deviations-from-m of the next point (coord1/coord3 raw; 0/2 exact)
        const float y1 = fmaf(DT, xa, r1);       // next1 - m1 (uncentered)
        const float y3 = fmaf(DT, ta, r3);       // next3 - m3 (uncentered)
        const float dev0 = fmaf(DT, r1, r0);     // next0 - n0 (exactly zero-mean)
        const float dev2 = fmaf(DT, r3, r2);     // next2 - n2 (exactly zero-mean)

        // ---- per-lane moment products ----
        float a1 = wgt * y1, a3 = wgt * y3;
        const float t0 = cw * dev0, t1 = cw * y1, t2 = cw * dev2, t3m = cw * y3;
        float p11 = t1 * y1, p13 = t1 * y3, p33 = t3m * y3;
        float p10 = t0 * y1, p30 = t0 * y3, p21 = t2 * y1, p32 = t2 * y3;

        // ---- 9 parallel butterfly reductions (all lanes get sums) ----
        #pragma unroll
        for (int o = 16; o > 0; o >>= 1) {
            a1  += __shfl_xor_sync(0xffffffffu, a1,  o);
            a3  += __shfl_xor_sync(0xffffffffu, a3,  o);
            p11 += __shfl_xor_sync(0xffffffffu, p11, o);
            p13 += __shfl_xor_sync(0xffffffffu, p13, o);
            p33 += __shfl_xor_sync(0xffffffffu, p33, o);
            p10 += __shfl_xor_sync(0xffffffffu, p10, o);
            p30 += __shfl_xor_sync(0xffffffffu, p30, o);
            p21 += __shfl_xor_sync(0xffffffffu, p21, o);
            p32 += __shfl_xor_sync(0xffffffffu, p32, o);
        }

        // ---- analytic linear-coordinate covariance entries (exact) ----
        const float A0 = fmaf(DT, S10, S00);
        const float A1v = DT * S11;
        const float C0 = fmaf(DT, S30, S20);
        const float C1 = fmaf(DT, S31, S21);
        const float C2v = fmaf(DT, S32, S22);
        const float C3 = DT * S33;
        const float c00 = fmaf(A1v, A1v, A0 * A0) + DIAG_ADD5;
        const float c20 = fmaf(A1v, C1, A0 * C0);
        const float c22 = fmaf(C3, C3, fmaf(C2v, C2v, fmaf(C1, C1, C0 * C0))) + DIAG_ADD5;

        // ---- next mean + de-meaned moments (x5 prescaled) ----
        const float d1 = a1, d3 = a3;
        const float n0 = fmaf(DT, m1, m0);
        const float n2 = fmaf(DT, m3, m2);
        const float n1 = m1 + d1;
        const float n3 = m3 + d3;
        const float f1 = 5.f * d1, f3 = 5.f * d3;
        const float c11 = fmaf(-f1, d1, p11) + DIAG_ADD5;
        const float c31 = fmaf(-f1, d3, p13);
        const float c33 = fmaf(-f3, d3, p33) + DIAG_ADD5;
        const float c10 = p10, c30 = p30, c21 = p21, c32 = p32;

        // ---- next-step policy (independent of Cholesky; chains overlap) ----
        const float u_next = policy_u2(n0, n1, n2, n3, wa, wb, nmu2, L2, NL2E2);

        // ---- reward (closed form): n^T Q n + 0.2 * trace(Q * 5C) ----
        const float q = fmaf(n0, n0, fmaf(n1, n1, fmaf(10.f * n2, n2, n3 * n3)));
        const float tr = c00 + c11 + fmaf(10.f, c22, c33);
        reward -= fmaf(0.2f, tr, q);

        // ---- 4x4 Cholesky via rsqrt (output is sqrt(5)*S) ----
        const float rr0 = rsqrtf(c00);
        S00 = c00 * rr0;
        S10 = c10 * rr0; S20 = c20 * rr0; S30 = c30 * rr0;
        const float a11 = fmaf(-S10, S10, c11);
        const float rr1 = rsqrtf(a11);
        S11 = a11 * rr1;
        S21 = fmaf(-S20, S10, c21) * rr1;
        S31 = fmaf(-S30, S10, c31) * rr1;
        const float a22 = fmaf(-S21, S21, fmaf(-S20, S20, c22));
        const float rr2 = rsqrtf(a22);
        S22 = a22 * rr2;
        S32 = fmaf(-S31, S21, fmaf(-S30, S20, c32)) * rr2;
        const float a33 = fmaf(-S32, S32, fmaf(-S31, S31, fmaf(-S30, S30, c33)));
        S33 = a33 * rsqrtf(a33);

        m0 = n0; m1 = n1; m2 = n2; m3 = n3;
        u = u_next;
    }

    if (lane == 0) out[0] = reward;
}

extern "C" void kernel_launch(void* const* d_in, const int* in_sizes, int n_in,
                              void* d_out, int out_size) {
    (void)in_sizes; (void)n_in; (void)out_size;
    horizon_reward_kernel<<<1, 32>>>((const float*)d_in[0], (float*)d_out);
}

// round 9
// speedup vs baseline: 1.4009x; 1.0793x over previous
#include <cuda_runtime.h>
#include <math.h>

// HorizonReward: collapsed UT cartpole rollout — SIMT sigma points,
// 16-lane (4-stage) SHFL reductions, affine-l policy split.
// redux.sync.add.f32 does NOT exist on sm_103a (R8 ptxas error) — SHFL it is.
// Latency-cycle surgery:
//   - both warp reductions use 16-lane domains (lower/upper halves hold
//     identical values) -> 4 dependent SHFL stages instead of 5
//   - policy l-vector = l_base(n0,m1,n2,m3) + L1*d1 + L3*d3 : bases computed
//     in the moment-reduction shadow, only 2 fma2 on the critical path
//   - dynamics pre-u terms (tk*s, 9.8*s, rcp-denominator) hoisted before u
// Covariance: R7's verified uncentered-moment scheme, x5-prescaled so
// chol() yields sqrt(5)*S directly; linear-coordinate entries analytic.

typedef unsigned long long u64;

__device__ __forceinline__ u64 pk(float lo, float hi) {
    u64 r; asm("mov.b64 %0,{%1,%2};" : "=l"(r) : "f"(lo), "f"(hi)); return r;
}
__device__ __forceinline__ void upk(u64 a, float& x, float& y) {
    asm("mov.b64 {%0,%1},%2;" : "=f"(x), "=f"(y) : "l"(a));
}
__device__ __forceinline__ u64 sp2(float s) { return pk(s, s); }
__device__ __forceinline__ u64 fma2_(u64 a, u64 b, u64 c) {
    u64 d; asm("fma.rn.f32x2 %0,%1,%2,%3;" : "=l"(d) : "l"(a), "l"(b), "l"(c)); return d;
}
__device__ __forceinline__ u64 mul2_(u64 a, u64 b) {
    u64 d; asm("mul.rn.f32x2 %0,%1,%2;" : "=l"(d) : "l"(a), "l"(b)); return d;
}
__device__ __forceinline__ u64 add2_(u64 a, u64 b) {
    u64 d; asm("add.rn.f32x2 %0,%1,%2;" : "=l"(d) : "l"(a), "l"(b)); return d;
}
__device__ __forceinline__ float rcp_(float x) {
    float r; asm("rcp.approx.f32 %0,%1;" : "=f"(r) : "f"(x)); return r;
}
__device__ __forceinline__ float ex2_(float x) {
    float r; asm("ex2.approx.f32 %0,%1;" : "=f"(r) : "f"(x)); return r;
}
// 4-stage butterfly over 16-lane halves (halves hold identical values).
__device__ __forceinline__ float red16(float x) {
    x += __shfl_xor_sync(0xffffffffu, x, 8);
    x += __shfl_xor_sync(0xffffffffu, x, 4);
    x += __shfl_xor_sync(0xffffffffu, x, 2);
    x += __shfl_xor_sync(0xffffffffu, x, 1);
    return x;
}

__global__ __launch_bounds__(32, 1)
void horizon_reward_kernel(const float* __restrict__ p, float* __restrict__ out)
{
    const int lane = threadIdx.x & 31;
    const int jj = lane & 15;            // 16-lane replicated layout

    // ---- policy params: lane jj handles RBFs jj, jj+16 (chain A) and
    //      jj+32, jj+48 (chain B, zero-padded past 50) ----
    u64 nmuA[4], LA[10], nmuB[4], LB[10];
    float wA0, wA1, wB0, wB1;
    {
        const int a0 = jj, a1 = jj + 16, b0 = jj + 32, b1 = jj + 48;
        const bool hb1 = (b1 < 50);      // b0 = jj+32 <= 47 always valid
        wA0 = p[a0]; wA1 = p[a1];
        wB0 = p[b0]; wB1 = hb1 ? p[b1] : 0.f;
        #pragma unroll
        for (int k = 0; k < 4; ++k) {
            nmuA[k] = pk(-p[50 + k * 50 + a0], -p[50 + k * 50 + a1]);
            nmuB[k] = pk(-p[50 + k * 50 + b0], hb1 ? -p[50 + k * 50 + b1] : 0.f);
        }
        #pragma unroll
        for (int t = 0; t < 10; ++t) {
            LA[t] = pk(p[250 + a0 * 10 + t], p[250 + a1 * 10 + t]);
            LB[t] = pk(p[250 + b0 * 10 + t], hb1 ? p[250 + b1 * 10 + t] : 0.f);
        }
    }

    const float DT = 0.05f;
    const float K1 = 0.05f / 1.1f;
    const float K3 = 0.5f * (4.0f / 3.0f);
    const float K2 = 0.5f * 0.1f / 1.1f;
    const float INV11 = 1.0f / 1.1f;
    const float DIAG_ADD5 = 5.0f * (0.01f * 0.05f + 2.0f * 1e-6f);
    const float NL2E = -1.4426950408889634f;
    const u64 NL2E2 = sp2(NL2E);

    // ---- per-lane sigma-point role (pt 0 = center, 1-4 = +col, 5-8 = -col,
    //      9-15 dummy); FULL weights (16-lane reduction counts each once) ----
    const int pt = jj;
    const int col = (pt == 0) ? 3 : ((pt - 1) & 3);
    const float sgn = (pt >= 1 && pt <= 4) ? 1.f : ((pt >= 5 && pt <= 8) ? -1.f : 0.f);
    const bool valid = (pt <= 8);
    const float wgt = (pt == 0) ? 0.2f : (valid ? 0.1f : 0.f);
    const float cw  = (pt == 0) ? 1.0f : (valid ? 0.5f : 0.f);   // 5*w
    const bool isC0 = (col == 0), isC1 = (col == 1), isC2 = (col == 2);

    // ---- state (warp-uniform): mean + scaled Cholesky sqrt(5)*chol(C) ----
    float m0 = 0.f, m1 = 0.f, m2 = 0.1f, m3 = 0.f;
    const float r0i = 2.23606797749979f * 1e-3f;
    float S00 = r0i, S10 = 0.f, S20 = 0.f, S30 = 0.f;
    float S11 = r0i, S21 = 0.f, S31 = 0.f;
    float S22 = r0i, S32 = 0.f;
    float S33 = r0i;

    // ---- initial u = policy(m) (full evaluation) ----
    float u;
    {
        u64 d0 = add2_(sp2(m0), nmuA[0]), d1 = add2_(sp2(m1), nmuA[1]);
        u64 d2 = add2_(sp2(m2), nmuA[2]), d3 = add2_(sp2(m3), nmuA[3]);
        u64 l0 = mul2_(LA[0], d0);
        l0 = fma2_(LA[4], d1, l0); l0 = fma2_(LA[5], d2, l0); l0 = fma2_(LA[7], d3, l0);
        u64 l1 = mul2_(LA[1], d1); l1 = fma2_(LA[6], d2, l1); l1 = fma2_(LA[8], d3, l1);
        u64 l2 = mul2_(LA[2], d2); l2 = fma2_(LA[9], d3, l2);
        u64 l3 = mul2_(LA[3], d3);
        u64 qA = fma2_(l1, l1, mul2_(l0, l0));
        qA = add2_(qA, fma2_(l3, l3, mul2_(l2, l2)));
        qA = mul2_(qA, NL2E2);
        d0 = add2_(sp2(m0), nmuB[0]); d1 = add2_(sp2(m1), nmuB[1]);
        d2 = add2_(sp2(m2), nmuB[2]); d3 = add2_(sp2(m3), nmuB[3]);
        l0 = mul2_(LB[0], d0);
        l0 = fma2_(LB[4], d1, l0); l0 = fma2_(LB[5], d2, l0); l0 = fma2_(LB[7], d3, l0);
        l1 = mul2_(LB[1], d1); l1 = fma2_(LB[6], d2, l1); l1 = fma2_(LB[8], d3, l1);
        l2 = mul2_(LB[2], d2); l2 = fma2_(LB[9], d3, l2);
        l3 = mul2_(LB[3], d3);
        u64 qB = fma2_(l1, l1, mul2_(l0, l0));
        qB = add2_(qB, fma2_(l3, l3, mul2_(l2, l2)));
        qB = mul2_(qB, NL2E2);
        float qa0, qa1, qb0, qb1;
        upk(qA, qa0, qa1); upk(qB, qb0, qb1);
        float acc = fmaf(wA0, ex2_(qa0), wA1 * ex2_(qa1))
                  + fmaf(wB0, ex2_(qb0), wB1 * ex2_(qb1));
        acc = red16(acc);
        u = fminf(fmaxf(acc, -10.f), 10.f);
    }

    float reward = 0.f;

    #pragma unroll 1
    for (int t = 0; t < 60; ++t) {
        // ======== S-dependent pre-u work (hidden under prev policy reduce) ====
        const float r0s = isC0 ? S00 : 0.f;
        const float r1s = isC0 ? S10 : (isC1 ? S11 : 0.f);
        const float r2s = isC0 ? S20 : (isC1 ? S21 : (isC2 ? S22 : 0.f));
        const float r3s = isC0 ? S30 : (isC1 ? S31 : (isC2 ? S32 : S33));
        const float r0 = sgn * r0s, r1 = sgn * r1s, r2 = sgn * r2s, r3 = sgn * r3s;

        const float th = m2 + r2, thd = m3 + r3;
        const float s = __sinf(th), c = __cosf(th);
        const float rd = rcp_(fmaf(-K2 * c, c, K3));
        const float tks = ((thd * thd) * K1) * s;    // pre-u part of temp
        const float g98 = 9.8f * s;

        // next linear-coordinate means (u-independent)
        const float n0 = fmaf(DT, m1, m0);
        const float n2 = fmaf(DT, m3, m2);
        // exactly-zero-mean linear deviations
        const float dev0 = fmaf(DT, r1, r0);
        const float dev2 = fmaf(DT, r3, r2);

        // analytic linear-coordinate covariance entries (exact)
        const float A0 = fmaf(DT, S10, S00);
        const float A1v = DT * S11;
        const float C0 = fmaf(DT, S30, S20);
        const float C1 = fmaf(DT, S31, S21);
        const float C2v = fmaf(DT, S32, S22);
        const float C3 = DT * S33;
        const float c00 = fmaf(A1v, A1v, A0 * A0) + DIAG_ADD5;
        const float c20 = fmaf(A1v, C1, A0 * C0);
        const float c22 = fmaf(C3, C3, fmaf(C2v, C2v, fmaf(C1, C1, C0 * C0))) + DIAG_ADD5;

        // ---- policy l-vector BASES at (n0, m1, n2, m3): u/d-independent ----
        const u64 a0c = add2_(sp2(n0), nmuA[0]), a1m = add2_(sp2(m1), nmuA[1]);
        const u64 a2c = add2_(sp2(n2), nmuA[2]), a3m = add2_(sp2(m3), nmuA[3]);
        u64 l0bA = mul2_(LA[0], a0c);
        l0bA = fma2_(LA[4], a1m, l0bA); l0bA = fma2_(LA[5], a2c, l0bA); l0bA = fma2_(LA[7], a3m, l0bA);
        u64 l1bA = mul2_(LA[1], a1m); l1bA = fma2_(LA[6], a2c, l1bA); l1bA = fma2_(LA[8], a3m, l1bA);
        u64 l2bA = mul2_(LA[2], a2c); l2bA = fma2_(LA[9], a3m, l2bA);
        u64 l3bA = mul2_(LA[3], a3m);
        const u64 b0c = add2_(sp2(n0), nmuB[0]), b1m = add2_(sp2(m1), nmuB[1]);
        const u64 b2c = add2_(sp2(n2), nmuB[2]), b3m = add2_(sp2(m3), nmuB[3]);
        u64 l0bB = mul2_(LB[0], b0c);
        l0bB = fma2_(LB[4], b1m, l0bB); l0bB = fma2_(LB[5], b2c, l0bB); l0bB = fma2_(LB[7], b3m, l0bB);
        u64 l1bB = mul2_(LB[1], b1m); l1bB = fma2_(LB[6], b2c, l1bB); l1bB = fma2_(LB[8], b3m, l1bB);
        u64 l2bB = mul2_(LB[2], b2c); l2bB = fma2_(LB[9], b3m, l2bB);
        u64 l3bB = mul2_(LB[3], b3m);

        // ================== u arrives: short post-u chain ====================
        const float ud = u * INV11;
        const float temp = tks + ud;
        const float num = fmaf(-c, temp, g98);
        const float ta = num * rd;
        const float xa = fmaf(-K1, ta * c, temp);
        const float y1 = fmaf(DT, xa, r1);      // next1 - m1 (uncentered)
        const float y3 = fmaf(DT, ta, r3);      // next3 - m3 (uncentered)

        // means first (on the u-path)
        const float d1 = red16(wgt * y1);
        const float d3 = red16(wgt * y3);

        // moment reductions (pipelined; consumed only by the Cholesky)
        const float t0 = cw * dev0, t1 = cw * y1, t2 = cw * dev2, t3m = cw * y3;
        const float p11 = red16(t1 * y1);
        const float p13 = red16(t1 * y3);
        const float p33 = red16(t3m * y3);
        const float p10 = red16(t0 * y1);
        const float p30 = red16(t0 * y3);
        const float p21 = red16(t2 * y1);
        const float p32 = red16(t2 * y3);

        // ---- policy: 2 fma2 fix-up per chain, q-tree, ex2, combine, reduce ----
        const u64 d1_2 = sp2(d1), d3_2 = sp2(d3);
        u64 l0 = fma2_(LA[4], d1_2, fma2_(LA[7], d3_2, l0bA));
        u64 l1 = fma2_(LA[1], d1_2, fma2_(LA[8], d3_2, l1bA));
        u64 l2 = fma2_(LA[9], d3_2, l2bA);
        u64 l3 = fma2_(LA[3], d3_2, l3bA);
        u64 qA = fma2_(l1, l1, mul2_(l0, l0));
        qA = add2_(qA, fma2_(l3, l3, mul2_(l2, l2)));
        qA = mul2_(qA, NL2E2);
        l0 = fma2_(LB[4], d1_2, fma2_(LB[7], d3_2, l0bB));
        l1 = fma2_(LB[1], d1_2, fma2_(LB[8], d3_2, l1bB));
        l2 = fma2_(LB[9], d3_2, l2bB);
        l3 = fma2_(LB[3], d3_2, l3bB);
        u64 qB = fma2_(l1, l1, mul2_(l0, l0));
        qB = add2_(qB, fma2_(l3, l3, mul2_(l2, l2)));
        qB = mul2_(qB, NL2E2);
        float qa0, qa1, qb0, qb1;
        upk(qA, qa0, qa1); upk(qB, qb0, qb1);
        float acc = fmaf(wA0, ex2_(qa0), wA1 * ex2_(qa1))
                  + fmaf(wB0, ex2_(qb0), wB1 * ex2_(qb1));
        acc = red16(acc);
        const float u_next = fminf(fmaxf(acc, -10.f), 10.f);

        // ---- state update + covariance + Cholesky (off the u-path) ----
        const float n1 = m1 + d1;
        const float n3 = m3 + d3;
        const float f1 = 5.f * d1, f3 = 5.f * d3;
        const float c11 = fmaf(-f1, d1, p11) + DIAG_ADD5;
        const float c31 = fmaf(-f1, d3, p13);
        const float c33 = fmaf(-f3, d3, p33) + DIAG_ADD5;
        const float c10 = p10, c30 = p30, c21 = p21, c32 = p32;

        // reward: n^T Q n + 0.2 * trace(Q * 5C)
        const float q = fmaf(n0, n0, fmaf(n1, n1, fmaf(10.f * n2, n2, n3 * n3)));
        const float tr = c00 + c11 + fmaf(10.f, c22, c33);
        reward -= fmaf(0.2f, tr, q);

        // 4x4 Cholesky via rsqrt (output is sqrt(5)*S)
        const float rr0 = rsqrtf(c00);
        S00 = c00 * rr0;
        S10 = c10 * rr0; S20 = c20 * rr0; S30 = c30 * rr0;
        const float a11 = fmaf(-S10, S10, c11);
        const float rr1 = rsqrtf(a11);
        S11 = a11 * rr1;
        S21 = fmaf(-S20, S10, c21) * rr1;
        S31 = fmaf(-S30, S10, c31) * rr1;
        const float a22 = fmaf(-S21, S21, fmaf(-S20, S20, c22));
        const float rr2 = rsqrtf(a22);
        S22 = a22 * rr2;
        S32 = fmaf(-S31, S21, fmaf(-S30, S20, c32)) * rr2;
        const float a33 = fmaf(-S32, S32, fmaf(-S31, S31, fmaf(-S30, S30, c33)));
        S33 = a33 * rsqrtf(a33);

        m0 = n0; m1 = n1; m2 = n2; m3 = n3;
        u = u_next;
    }

    if (lane == 0) out[0] = reward;
}

extern "C" void kernel_launch(void* const* d_in, const int* in_sizes, int n_in,
                              void* d_out, int out_size) {
    (void)in_sizes; (void)n_in; (void)out_size;
    horizon_reward_kernel<<<1, 32>>>((const float*)d_in[0], (float*)d_out);
}

// round 10
// speedup vs baseline: 1.4031x; 1.0015x over previous
#include <cuda_runtime.h>
#include <math.h>

// HorizonReward: collapsed UT cartpole rollout — parallel-gather reductions.
// Butterfly reductions have 4-5 serially dependent SHFL stages (~104-130 cyc);
// this version replaces them with PARALLEL shuffle structures:
//   - sigma means/moments: every lane gathers all 9 (y1,y3) via independent
//     shfl.idx (one 26-cyc latency), then computes d1,d3 and all 7 moments
//     locally in packed f32x2 (z_j=(y1_j,y3_j): squares/crosses/pair-diffs
//     fall out naturally)
//   - policy sum: radix-4 two-stage (3 parallel shfl.xor per stage) = ~68 cyc
// Rest as verified R9: pre-u dynamics hoist, affine-l policy bases, analytic
// linear-coordinate covariance, uncentered moments, x5-prescaled chol.

typedef unsigned long long u64;

__device__ __forceinline__ u64 pk(float lo, float hi) {
    u64 r; asm("mov.b64 %0,{%1,%2};" : "=l"(r) : "f"(lo), "f"(hi)); return r;
}
__device__ __forceinline__ void upk(u64 a, float& x, float& y) {
    asm("mov.b64 {%0,%1},%2;" : "=f"(x), "=f"(y) : "l"(a));
}
__device__ __forceinline__ u64 sp2(float s) { return pk(s, s); }
__device__ __forceinline__ u64 fma2_(u64 a, u64 b, u64 c) {
    u64 d; asm("fma.rn.f32x2 %0,%1,%2,%3;" : "=l"(d) : "l"(a), "l"(b), "l"(c)); return d;
}
__device__ __forceinline__ u64 mul2_(u64 a, u64 b) {
    u64 d; asm("mul.rn.f32x2 %0,%1,%2;" : "=l"(d) : "l"(a), "l"(b)); return d;
}
__device__ __forceinline__ u64 add2_(u64 a, u64 b) {
    u64 d; asm("add.rn.f32x2 %0,%1,%2;" : "=l"(d) : "l"(a), "l"(b)); return d;
}
__device__ __forceinline__ float rcp_(float x) {
    float r; asm("rcp.approx.f32 %0,%1;" : "=f"(r) : "f"(x)); return r;
}
__device__ __forceinline__ float ex2_(float x) {
    float r; asm("ex2.approx.f32 %0,%1;" : "=f"(r) : "f"(x)); return r;
}
// radix-4 two-stage 16-lane reduction (parallel shfls within each stage)
__device__ __forceinline__ float red16_r4(float x) {
    const float a = __shfl_xor_sync(0xffffffffu, x, 4);
    const float b = __shfl_xor_sync(0xffffffffu, x, 8);
    const float c = __shfl_xor_sync(0xffffffffu, x, 12);
    x = (x + a) + (b + c);
    const float d = __shfl_xor_sync(0xffffffffu, x, 1);
    const float e = __shfl_xor_sync(0xffffffffu, x, 2);
    const float f = __shfl_xor_sync(0xffffffffu, x, 3);
    return (x + d) + (e + f);
}

__global__ __launch_bounds__(32, 1)
void horizon_reward_kernel(const float* __restrict__ p, float* __restrict__ out)
{
    const int lane = threadIdx.x & 31;
    const int jj = lane & 15;            // 16-lane replicated layout

    // ---- policy params: lane jj handles RBFs jj, jj+16 (chain A) and
    //      jj+32, jj+48 (chain B, zero-padded past 50) ----
    u64 nmuA[4], LA[10], nmuB[4], LB[10];
    float wA0, wA1, wB0, wB1;
    {
        const int a0 = jj, a1 = jj + 16, b0 = jj + 32, b1 = jj + 48;
        const bool hb1 = (b1 < 50);
        wA0 = p[a0]; wA1 = p[a1];
        wB0 = p[b0]; wB1 = hb1 ? p[b1] : 0.f;
        #pragma unroll
        for (int k = 0; k < 4; ++k) {
            nmuA[k] = pk(-p[50 + k * 50 + a0], -p[50 + k * 50 + a1]);
            nmuB[k] = pk(-p[50 + k * 50 + b0], hb1 ? -p[50 + k * 50 + b1] : 0.f);
        }
        #pragma unroll
        for (int t = 0; t < 10; ++t) {
            LA[t] = pk(p[250 + a0 * 10 + t], p[250 + a1 * 10 + t]);
            LB[t] = pk(p[250 + b0 * 10 + t], hb1 ? p[250 + b1 * 10 + t] : 0.f);
        }
    }

    const float DT = 0.05f;
    const float K1 = 0.05f / 1.1f;
    const float K3 = 0.5f * (4.0f / 3.0f);
    const float K2 = 0.5f * 0.1f / 1.1f;
    const float INV11 = 1.0f / 1.1f;
    const float DIAG_ADD5 = 5.0f * (0.01f * 0.05f + 2.0f * 1e-6f);
    const u64 NL2E2 = sp2(-1.4426950408889634f);
    const u64 NM1_2 = sp2(-1.f);
    const u64 W0_2 = sp2(0.2f), WI_2 = sp2(0.1f), HALF2 = sp2(0.5f);

    // ---- per-lane sigma-point role (lanes 0-8 own points; 9-15 dummy;
    //      lanes 16-31 mirror for shfl convergence but are never gathered) ----
    const int pt = jj;
    const int col = (pt == 0) ? 3 : ((pt - 1) & 3);
    const float sgn = (pt >= 1 && pt <= 4) ? 1.f : ((pt >= 5 && pt <= 8) ? -1.f : 0.f);
    const bool isC0 = (col == 0), isC1 = (col == 1), isC2 = (col == 2);

    // ---- state (warp-uniform): mean + scaled Cholesky sqrt(5)*chol(C) ----
    float m0 = 0.f, m1 = 0.f, m2 = 0.1f, m3 = 0.f;
    const float r0i = 2.23606797749979f * 1e-3f;
    float S00 = r0i, S10 = 0.f, S20 = 0.f, S30 = 0.f;
    float S11 = r0i, S21 = 0.f, S31 = 0.f;
    float S22 = r0i, S32 = 0.f;
    float S33 = r0i;

    // ---- initial u = policy(m) ----
    float u;
    {
        u64 d0 = add2_(sp2(m0), nmuA[0]), d1 = add2_(sp2(m1), nmuA[1]);
        u64 d2 = add2_(sp2(m2), nmuA[2]), d3 = add2_(sp2(m3), nmuA[3]);
        u64 l0 = mul2_(LA[0], d0);
        l0 = fma2_(LA[4], d1, l0); l0 = fma2_(LA[5], d2, l0); l0 = fma2_(LA[7], d3, l0);
        u64 l1 = mul2_(LA[1], d1); l1 = fma2_(LA[6], d2, l1); l1 = fma2_(LA[8], d3, l1);
        u64 l2 = mul2_(LA[2], d2); l2 = fma2_(LA[9], d3, l2);
        u64 l3 = mul2_(LA[3], d3);
        u64 qA = fma2_(l1, l1, mul2_(l0, l0));
        qA = add2_(qA, fma2_(l3, l3, mul2_(l2, l2)));
        qA = mul2_(qA, NL2E2);
        d0 = add2_(sp2(m0), nmuB[0]); d1 = add2_(sp2(m1), nmuB[1]);
        d2 = add2_(sp2(m2), nmuB[2]); d3 = add2_(sp2(m3), nmuB[3]);
        l0 = mul2_(LB[0], d0);
        l0 = fma2_(LB[4], d1, l0); l0 = fma2_(LB[5], d2, l0); l0 = fma2_(LB[7], d3, l0);
        l1 = mul2_(LB[1], d1); l1 = fma2_(LB[6], d2, l1); l1 = fma2_(LB[8], d3, l1);
        l2 = mul2_(LB[2], d2); l2 = fma2_(LB[9], d3, l2);
        l3 = mul2_(LB[3], d3);
        u64 qB = fma2_(l1, l1, mul2_(l0, l0));
        qB = add2_(qB, fma2_(l3, l3, mul2_(l2, l2)));
        qB = mul2_(qB, NL2E2);
        float qa0, qa1, qb0, qb1;
        upk(qA, qa0, qa1); upk(qB, qb0, qb1);
        float acc = fmaf(wA0, ex2_(qa0), wA1 * ex2_(qa1))
                  + fmaf(wB0, ex2_(qb0), wB1 * ex2_(qb1));
        acc = red16_r4(acc);
        u = fminf(fmaxf(acc, -10.f), 10.f);
    }

    float reward = 0.f;

    #pragma unroll 1
    for (int t = 0; t < 60; ++t) {
        // ======== S-dependent pre-u work (hidden under prev policy reduce) ====
        const float r1 = sgn * (isC0 ? S10 : (isC1 ? S11 : 0.f));
        const float r2 = sgn * (isC0 ? S20 : (isC1 ? S21 : (isC2 ? S22 : 0.f)));
        const float r3 = sgn * (isC0 ? S30 : (isC1 ? S31 : (isC2 ? S32 : S33)));

        const float th = m2 + r2, thd = m3 + r3;
        const float s = __sinf(th), c = __cosf(th);
        const float rd = rcp_(fmaf(-K2 * c, c, K3));
        const float tks = ((thd * thd) * K1) * s;
        const float g98 = 9.8f * s;

        const float n0 = fmaf(DT, m1, m0);
        const float n2 = fmaf(DT, m3, m2);

        // analytic linear-coordinate covariance entries (exact; halved forms
        // folded for the cross-moment formulas)
        const float A0 = fmaf(DT, S10, S00);
        const float A1v = DT * S11;
        const float C0 = fmaf(DT, S30, S20);
        const float C1 = fmaf(DT, S31, S21);
        const float C2v = fmaf(DT, S32, S22);
        const float C3 = DT * S33;
        const float c00 = fmaf(A1v, A1v, A0 * A0) + DIAG_ADD5;
        const float c20 = fmaf(A1v, C1, A0 * C0);
        const float c22 = fmaf(C3, C3, fmaf(C2v, C2v, fmaf(C1, C1, C0 * C0))) + DIAG_ADD5;
        const u64 A0h2 = sp2(0.5f * A0), A1h2 = sp2(0.5f * A1v);
        const u64 C0h2 = sp2(0.5f * C0), C1h2 = sp2(0.5f * C1);
        const u64 C2h2 = sp2(0.5f * C2v), C3h2 = sp2(0.5f * C3);

        // ---- policy l-vector BASES at (n0, m1, n2, m3) ----
        const u64 a0c = add2_(sp2(n0), nmuA[0]), a1m = add2_(sp2(m1), nmuA[1]);
        const u64 a2c = add2_(sp2(n2), nmuA[2]), a3m = add2_(sp2(m3), nmuA[3]);
        u64 l0bA = mul2_(LA[0], a0c);
        l0bA = fma2_(LA[4], a1m, l0bA); l0bA = fma2_(LA[5], a2c, l0bA); l0bA = fma2_(LA[7], a3m, l0bA);
        u64 l1bA = mul2_(LA[1], a1m); l1bA = fma2_(LA[6], a2c, l1bA); l1bA = fma2_(LA[8], a3m, l1bA);
        u64 l2bA = mul2_(LA[2], a2c); l2bA = fma2_(LA[9], a3m, l2bA);
        u64 l3bA = mul2_(LA[3], a3m);
        const u64 b0c = add2_(sp2(n0), nmuB[0]), b1m = add2_(sp2(m1), nmuB[1]);
        const u64 b2c = add2_(sp2(n2), nmuB[2]), b3m = add2_(sp2(m3), nmuB[3]);
        u64 l0bB = mul2_(LB[0], b0c);
        l0bB = fma2_(LB[4], b1m, l0bB); l0bB = fma2_(LB[5], b2c, l0bB); l0bB = fma2_(LB[7], b3m, l0bB);
        u64 l1bB = mul2_(LB[1], b1m); l1bB = fma2_(LB[6], b2c, l1bB); l1bB = fma2_(LB[8], b3m, l1bB);
        u64 l2bB = mul2_(LB[2], b2c); l2bB = fma2_(LB[9], b3m, l2bB);
        u64 l3bB = mul2_(LB[3], b3m);

        // ================== u arrives: short post-u chain ====================
        const float ud = u * INV11;
        const float temp = tks + ud;
        const float num = fmaf(-c, temp, g98);
        const float ta = num * rd;
        const float xa = fmaf(-K1, ta * c, temp);
        const float y1 = fmaf(DT, xa, r1);      // next1 - m1 (uncentered)
        const float y3 = fmaf(DT, ta, r3);      // next3 - m3 (uncentered)

        // ---- gather all 9 (y1,y3) — 18 PARALLEL shfl.idx, one latency ----
        u64 z[9];
        #pragma unroll
        for (int j = 0; j < 9; ++j) {
            const float g1 = __shfl_sync(0xffffffffu, y1, j);
            const float g3 = __shfl_sync(0xffffffffu, y3, j);
            z[j] = pk(g1, g3);
        }

        // ---- packed means: d13 = 0.2 z0 + 0.1 sum(z1..z8) ----
        const u64 sA = add2_(add2_(z[1], z[2]), add2_(z[3], z[4]));
        const u64 sB = add2_(add2_(z[5], z[6]), add2_(z[7], z[8]));
        const u64 d13 = fma2_(WI_2, add2_(sA, sB), mul2_(W0_2, z[0]));
        float d1, d3; upk(d13, d1, d3);

        // ---- policy: 2 fma2 fix-up per chain, q-tree, ex2, radix-4 reduce ----
        const u64 d1_2 = sp2(d1), d3_2 = sp2(d3);
        {
            u64 l0 = fma2_(LA[4], d1_2, fma2_(LA[7], d3_2, l0bA));
            u64 l1 = fma2_(LA[1], d1_2, fma2_(LA[8], d3_2, l1bA));
            u64 l2 = fma2_(LA[9], d3_2, l2bA);
            u64 l3 = fma2_(LA[3], d3_2, l3bA);
            u64 qA = fma2_(l1, l1, mul2_(l0, l0));
            qA = add2_(qA, fma2_(l3, l3, mul2_(l2, l2)));
            qA = mul2_(qA, NL2E2);
            l0 = fma2_(LB[4], d1_2, fma2_(LB[7], d3_2, l0bB));
            l1 = fma2_(LB[1], d1_2, fma2_(LB[8], d3_2, l1bB));
            l2 = fma2_(LB[9], d3_2, l2bB);
            l3 = fma2_(LB[3], d3_2, l3bB);
            u64 qB = fma2_(l1, l1, mul2_(l0, l0));
            qB = add2_(qB, fma2_(l3, l3, mul2_(l2, l2)));
            qB = mul2_(qB, NL2E2);
            float qa0, qa1, qb0, qb1;
            upk(qA, qa0, qa1); upk(qB, qb0, qb1);
            float acc = fmaf(wA0, ex2_(qa0), wA1 * ex2_(qa1))
                      + fmaf(wB0, ex2_(qb0), wB1 * ex2_(qb1));
            acc = red16_r4(acc);
            u = fminf(fmaxf(acc, -10.f), 10.f);
        }

        // ---- local moments from gathered z (off the u-path) ----
        // pair differences gz_j = z_j - z_{j+4}
        const u64 gz1 = fma2_(z[5], NM1_2, z[1]);
        const u64 gz2 = fma2_(z[6], NM1_2, z[2]);
        const u64 gz3 = fma2_(z[7], NM1_2, z[3]);
        const u64 gz4 = fma2_(z[8], NM1_2, z[4]);
        // cross moments with linear coords: (p10,p30) and (p21,p32)
        const u64 p1030 = fma2_(A1h2, gz2, mul2_(A0h2, gz1));
        u64 p2132 = fma2_(C1h2, gz2, mul2_(C0h2, gz1));
        p2132 = fma2_(C2h2, gz3, p2132);
        p2132 = fma2_(C3h2, gz4, p2132);
        float p10, p30, p21, p32;
        upk(p1030, p10, p30); upk(p2132, p21, p32);
        // packed squares: (p11,p33) = z0^2 + 0.5*sum(zj^2)
        u64 sq = mul2_(z[1], z[1]);
        sq = fma2_(z[2], z[2], sq); sq = fma2_(z[3], z[3], sq);
        sq = fma2_(z[4], z[4], sq); sq = fma2_(z[5], z[5], sq);
        sq = fma2_(z[6], z[6], sq); sq = fma2_(z[7], z[7], sq);
        sq = fma2_(z[8], z[8], sq);
        const u64 p1133 = fma2_(HALF2, sq, mul2_(z[0], z[0]));
        float p11, p33; upk(p1133, p11, p33);
        // scalar cross moment p13 = y1_0*y3_0 + 0.5*sum(y1_j*y3_j)
        float y1j[9], y3j[9];
        #pragma unroll
        for (int j = 0; j < 9; ++j) upk(z[j], y1j[j], y3j[j]);
        float xs = y1j[1] * y3j[1];
        xs = fmaf(y1j[2], y3j[2], xs); xs = fmaf(y1j[3], y3j[3], xs);
        xs = fmaf(y1j[4], y3j[4], xs); xs = fmaf(y1j[5], y3j[5], xs);
        xs = fmaf(y1j[6], y3j[6], xs); xs = fmaf(y1j[7], y3j[7], xs);
        xs = fmaf(y1j[8], y3j[8], xs);
        const float p13 = fmaf(0.5f, xs, y1j[0] * y3j[0]);

        // ---- de-meaned covariance entries (x5 prescaled) ----
        const float n1 = m1 + d1;
        const float n3 = m3 + d3;
        const float f1 = 5.f * d1, f3 = 5.f * d3;
        const float c11 = fmaf(-f1, d1, p11) + DIAG_ADD5;
        const float c31 = fmaf(-f1, d3, p13);
        const float c33 = fmaf(-f3, d3, p33) + DIAG_ADD5;
        const float c10 = p10, c30 = p30, c21 = p21, c32 = p32;

        // reward: n^T Q n + 0.2 * trace(Q * 5C)
        const float q = fmaf(n0, n0, fmaf(n1, n1, fmaf(10.f * n2, n2, n3 * n3)));
        const float tr = c00 + c11 + fmaf(10.f, c22, c33);
        reward -= fmaf(0.2f, tr, q);

        // 4x4 Cholesky via rsqrt (output is sqrt(5)*S)
        const float rr0 = rsqrtf(c00);
        S00 = c00 * rr0;
        S10 = c10 * rr0; S20 = c20 * rr0; S30 = c30 * rr0;
        const float a11 = fmaf(-S10, S10, c11);
        const float rr1 = rsqrtf(a11);
        S11 = a11 * rr1;
        S21 = fmaf(-S20, S10, c21) * rr1;
        S31 = fmaf(-S30, S10, c31) * rr1;
        const float a22 = fmaf(-S21, S21, fmaf(-S20, S20, c22));
        const float rr2 = rsqrtf(a22);
        S22 = a22 * rr2;
        S32 = fmaf(-S31, S21, fmaf(-S30, S20, c32)) * rr2;
        const float a33 = fmaf(-S32, S32, fmaf(-S31, S31, fmaf(-S30, S30, c33)));
        S33 = a33 * rsqrtf(a33);

        m0 = n0; m1 = n1; m2 = n2; m3 = n3;
    }

    if (lane == 0) out[0] = reward;
}

extern "C" void kernel_launch(void* const* d_in, const int* in_sizes, int n_in,
                              void* d_out, int out_size) {
    (void)in_sizes; (void)n_in; (void)out_size;
    horizon_reward_kernel<<<1, 32>>>((const float*)d_in[0], (float*)d_out);
}